// round 6
// baseline (speedup 1.0000x reference)
#include <cuda_runtime.h>
#include <cstdint>
#include <cstddef>

// Batched MHA: qkv [2048,144,384] f32, mask [1,4,144,144] f32 -> out [2048,144,128] f32
// B=2048, H=4, N=144, d=32. One CTA per (b,h); 160 threads = 5 warps.
// Warps 0-3 compute TWO m16 tiles each, warp 4 one tile (9 tiles = 144 rows).
// Key point: K/V B-fragments are m-independent, so a 2-tile warp reuses every
// K/V LDS.128 twice -> ~2x less smem read traffic (prev kernel was L1-bound at 81%).
// Q is NOT staged in smem: A-fragments load directly from GMEM (quad-coalesced).
// One-pass softmax without max subtraction (|scores| << 88). tf32 mma.sync.

#define SCALE_F 0.17677669529663687f
#define FULLM 0xffffffffu

__device__ __forceinline__ unsigned f2tf32(float f) {
    unsigned r;
    asm("cvt.rna.tf32.f32 %0, %1;" : "=r"(r) : "f"(f));
    return r;
}

__device__ __forceinline__ void mma_tf32(float* d,
    unsigned a0, unsigned a1, unsigned a2, unsigned a3,
    unsigned b0, unsigned b1)
{
    asm volatile(
        "mma.sync.aligned.m16n8k8.row.col.f32.tf32.tf32.f32 "
        "{%0,%1,%2,%3},{%4,%5,%6,%7},{%8,%9},{%0,%1,%2,%3};"
        : "+f"(d[0]), "+f"(d[1]), "+f"(d[2]), "+f"(d[3])
        : "r"(a0), "r"(a1), "r"(a2), "r"(a3), "r"(b0), "r"(b1));
}

constexpr int NSEQ = 144;
constexpr int STRQ = 36;                      // K permuted row stride (floats)
constexpr int STRV = 40;                      // V permuted row stride (floats)
constexpr int K_ELEMS = NSEQ * STRQ;          // 5184
constexpr int V_ELEMS = NSEQ * STRV;          // 5760
constexpr int SMEM_BYTES = (K_ELEMS + V_ELEMS) * 4;   // 43776 B

// MT = number of m16 tiles this warp owns (2 for warps 0-3, 1 for warp 4).
template<int MT>
__device__ __forceinline__ void attn_warp_body(
    const unsigned* __restrict__ Kp, const unsigned* __restrict__ Vp,
    const float* __restrict__ qbase,     // qkv + b*144*384 + h*32 (q plane)
    const float* __restrict__ mbase,     // mask + h*144*144
    float* __restrict__ obase,           // out + b*144*128 + h*32
    int m0base, int lane)
{
    const int qr = lane >> 2;     // 0..7
    const int qc = lane & 3;      // 0..3
    const int src0 = (lane & ~3) | (qc >> 1);
    const int src1 = src0 + 2;
    const bool odd = (qc & 1) != 0;

    // ---- Q A-fragments straight from GMEM (scaled, tf32) ----
    // k-group kk needs cols kk*8+qc and kk*8+qc+4  ==  qc+4j for j=2kk, 2kk+1
    unsigned aq0[MT][8], aq1[MT][8];
    #pragma unroll
    for (int t = 0; t < MT; t++) {
        const float* r0p = qbase + (m0base + t * 16 + qr) * 384;
        const float* r1p = r0p + 8 * 384;
        #pragma unroll
        for (int j = 0; j < 8; j++) {
            aq0[t][j] = f2tf32(r0p[qc + 4 * j] * SCALE_F);
            aq1[t][j] = f2tf32(r1p[qc + 4 * j] * SCALE_F);
        }
    }

    float o[MT][4][4];
    float l0[MT], l1[MT];
    const float* mr0[MT];
    #pragma unroll
    for (int t = 0; t < MT; t++) {
        l0[t] = 0.f; l1[t] = 0.f;
        mr0[t] = mbase + (m0base + t * 16 + qr) * NSEQ + 2 * qc;
        #pragma unroll
        for (int dt = 0; dt < 4; dt++) {
            o[t][dt][0] = 0.f; o[t][dt][1] = 0.f;
            o[t][dt][2] = 0.f; o[t][dt][3] = 0.f;
        }
    }

    // ---- stream over 144 key cols: 6 chunks x 3 n-tiles ----
    #pragma unroll
    for (int ch = 0; ch < 6; ch++) {
        float acc[MT][3][4];

        // S = Q @ K^T (+mask): K frags loaded ONCE per n-tile, reused by all MT tiles
        #pragma unroll
        for (int j = 0; j < 3; j++) {
            const int n0 = (ch * 3 + j) * 8;
            const uint4 B  = *(const uint4*)(Kp + (n0 + qr) * STRQ + qc * 8);
            const uint4 Bb = *(const uint4*)(Kp + (n0 + qr) * STRQ + qc * 8 + 4);
            #pragma unroll
            for (int t = 0; t < MT; t++) {
                float* a = acc[t][j];
                a[0] = 0.f; a[1] = 0.f; a[2] = 0.f; a[3] = 0.f;
                mma_tf32(a, aq0[t][0], aq1[t][0], aq0[t][1], aq1[t][1], B.x,  B.y);
                mma_tf32(a, aq0[t][2], aq1[t][2], aq0[t][3], aq1[t][3], B.z,  B.w);
                mma_tf32(a, aq0[t][4], aq1[t][4], aq0[t][5], aq1[t][5], Bb.x, Bb.y);
                mma_tf32(a, aq0[t][6], aq1[t][6], aq0[t][7], aq1[t][7], Bb.z, Bb.w);
                const float2 mv0 = *(const float2*)(mr0[t] + n0);
                const float2 mv1 = *(const float2*)(mr0[t] + 8 * NSEQ + n0);
                a[0] += mv0.x; a[1] += mv0.y;
                a[2] += mv1.x; a[3] += mv1.y;
            }
        }

        // P = exp(S); accumulate row sums
        #pragma unroll
        for (int j = 0; j < 3; j++) {
            #pragma unroll
            for (int t = 0; t < MT; t++) {
                float* a = acc[t][j];
                a[0] = __expf(a[0]); a[1] = __expf(a[1]);
                a[2] = __expf(a[2]); a[3] = __expf(a[3]);
                l0[t] += a[0] + a[1];
                l1[t] += a[2] + a[3];
            }
        }

        // O += P @ V: V frags loaded ONCE per k-tile, reused by all MT tiles
        #pragma unroll
        for (int j = 0; j < 3; j++) {
            const int krow = (ch * 3 + j) * 8;
            const uint4 Vl = *(const uint4*)(Vp + (krow + qc    ) * STRV + qr * 4);
            const uint4 Vh = *(const uint4*)(Vp + (krow + qc + 4) * STRV + qr * 4);
            #pragma unroll
            for (int t = 0; t < MT; t++) {
                const float* a = acc[t][j];
                const float s00 = __shfl_sync(FULLM, a[0], src0);
                const float s01 = __shfl_sync(FULLM, a[1], src0);
                const float s10 = __shfl_sync(FULLM, a[2], src0);
                const float s11 = __shfl_sync(FULLM, a[3], src0);
                const float t00 = __shfl_sync(FULLM, a[0], src1);
                const float t01 = __shfl_sync(FULLM, a[1], src1);
                const float t10 = __shfl_sync(FULLM, a[2], src1);
                const float t11 = __shfl_sync(FULLM, a[3], src1);
                const unsigned pa0 = f2tf32(odd ? s01 : s00);
                const unsigned pa1 = f2tf32(odd ? s11 : s10);
                const unsigned pa2 = f2tf32(odd ? t01 : t00);
                const unsigned pa3 = f2tf32(odd ? t11 : t10);
                mma_tf32(o[t][0], pa0, pa1, pa2, pa3, Vl.x, Vh.x);
                mma_tf32(o[t][1], pa0, pa1, pa2, pa3, Vl.y, Vh.y);
                mma_tf32(o[t][2], pa0, pa1, pa2, pa3, Vl.z, Vh.z);
                mma_tf32(o[t][3], pa0, pa1, pa2, pa3, Vl.w, Vh.w);
            }
        }
    }

    // ---- normalize + store ----
    #pragma unroll
    for (int t = 0; t < MT; t++) {
        float a0 = l0[t], a1 = l1[t];
        a0 += __shfl_xor_sync(FULLM, a0, 1);
        a0 += __shfl_xor_sync(FULLM, a0, 2);
        a1 += __shfl_xor_sync(FULLM, a1, 1);
        a1 += __shfl_xor_sync(FULLM, a1, 2);
        const float i0 = 1.f / a0;
        const float i1 = 1.f / a1;
        const int m0 = m0base + t * 16;
        #pragma unroll
        for (int dt = 0; dt < 4; dt++) {
            const int d = dt * 8 + 2 * qc;
            float2* p0 = (float2*)(obase + (m0 + qr    ) * 128 + d);
            float2* p1 = (float2*)(obase + (m0 + qr + 8) * 128 + d);
            *p0 = make_float2(o[t][dt][0] * i0, o[t][dt][1] * i0);
            *p1 = make_float2(o[t][dt][2] * i1, o[t][dt][3] * i1);
        }
    }
}

__global__ void __launch_bounds__(160, 3)
attn_kernel(const float* __restrict__ qkv,
            const float* __restrict__ mask,
            float* __restrict__ out)
{
    extern __shared__ unsigned sm[];
    unsigned* Kp = sm;                 // perm: orig col c -> i = (c%4)*8 + c/4
    unsigned* Vp = sm + K_ELEMS;       // perm: orig col c -> i = (c%8)*4 + c/8

    const int bh = blockIdx.x;
    const int b = bh >> 2;
    const int h = bh & 3;
    const int tid = threadIdx.x;

    // ---- Stage K, V into smem as tf32, fragment-permuted ----
    const float* gbase = qkv + (size_t)b * (NSEQ * 384) + h * 32;
    for (int idx = tid; idx < NSEQ * 8; idx += 160) {
        const int row = idx >> 3;
        const int c4  = (idx & 7) << 2;
        const float* g = gbase + row * 384 + c4;
        float4 k = *(const float4*)(g + 128);
        float4 v = *(const float4*)(g + 256);
        unsigned* kr_ = Kp + row * STRQ + (c4 >> 2);
        kr_[0]  = f2tf32(k.x);
        kr_[8]  = f2tf32(k.y);
        kr_[16] = f2tf32(k.z);
        kr_[24] = f2tf32(k.w);
        unsigned* vr_ = Vp + row * STRV + ((c4 & 7) << 2) + (c4 >> 3);
        vr_[0]  = f2tf32(v.x);
        vr_[4]  = f2tf32(v.y);
        vr_[8]  = f2tf32(v.z);
        vr_[12] = f2tf32(v.w);
    }
    __syncthreads();

    const int warp = tid >> 5;    // 0..4
    const int lane = tid & 31;

    const float* qbase = gbase;   // q plane shares base (cols 0..31 of the 384)
    const float* mbase = mask + h * (NSEQ * NSEQ);
    float* obase = out + (size_t)b * (NSEQ * 128) + h * 32;

    if (warp < 4) {
        attn_warp_body<2>(Kp, Vp, qbase, mbase, obase, warp * 32, lane);
    } else {
        attn_warp_body<1>(Kp, Vp, qbase, mbase, obase, 128, lane);
    }
}

extern "C" void kernel_launch(void* const* d_in, const int* in_sizes, int n_in,
                              void* d_out, int out_size)
{
    const float* qkv  = (const float*)d_in[0];
    const float* mask = (const float*)d_in[1];
    float* out = (float*)d_out;

    cudaFuncSetAttribute(attn_kernel,
                         cudaFuncAttributeMaxDynamicSharedMemorySize, SMEM_BYTES);
    attn_kernel<<<2048 * 4, 160, SMEM_BYTES>>>(qkv, mask, out);
}

// round 9
// speedup vs baseline: 1.0376x; 1.0376x over previous
#include <cuda_runtime.h>
#include <cstdint>
#include <cstddef>

// Batched MHA: qkv [2048,144,384] f32, mask [1,4,144,144] f32 -> out [2048,144,128] f32
// B=2048, H=4, N=144, d=32. One CTA per (b,h); 160 threads = 5 warps.
// Warps 0-3 compute TWO m16 tiles each, warp 4 one tile (9 tiles = 144 rows).
// K/V B-fragments are m-independent -> a 2-tile warp reuses each K/V LDS.128 twice
// (halves the dominant smem read traffic vs the 9-warp layout).
// FIX vs R5: Q staged in smem fragment-permuted (4 conflict-free LDS.128 per tile)
// instead of heavily-uncoalesced scalar GMEM loads.
// One-pass softmax without max subtraction (|scores| << 88). tf32 mma.sync.

#define SCALE_F 0.17677669529663687f
#define FULLM 0xffffffffu

__device__ __forceinline__ unsigned f2tf32(float f) {
    unsigned r;
    asm("cvt.rna.tf32.f32 %0, %1;" : "=r"(r) : "f"(f));
    return r;
}

__device__ __forceinline__ void mma_tf32(float* d,
    unsigned a0, unsigned a1, unsigned a2, unsigned a3,
    unsigned b0, unsigned b1)
{
    asm volatile(
        "mma.sync.aligned.m16n8k8.row.col.f32.tf32.tf32.f32 "
        "{%0,%1,%2,%3},{%4,%5,%6,%7},{%8,%9},{%0,%1,%2,%3};"
        : "+f"(d[0]), "+f"(d[1]), "+f"(d[2]), "+f"(d[3])
        : "r"(a0), "r"(a1), "r"(a2), "r"(a3), "r"(b0), "r"(b1));
}

constexpr int NSEQ = 144;
constexpr int STRQ = 36;                      // Q/K permuted row stride (floats)
constexpr int STRV = 40;                      // V permuted row stride (floats)
constexpr int QK_ELEMS = NSEQ * STRQ;         // 5184
constexpr int V_ELEMS  = NSEQ * STRV;         // 5760
constexpr int SMEM_BYTES = (2 * QK_ELEMS + V_ELEMS) * 4;   // 64512 B

// MT = number of m16 tiles this warp owns (2 for warps 0-3, 1 for warp 4).
template<int MT>
__device__ __forceinline__ void attn_warp_body(
    const unsigned* __restrict__ Qp,
    const unsigned* __restrict__ Kp, const unsigned* __restrict__ Vp,
    const float* __restrict__ mbase,     // mask + h*144*144
    float* __restrict__ obase,           // out + b*144*128 + h*32
    int m0base, int lane)
{
    const int qr = lane >> 2;     // 0..7
    const int qc = lane & 3;      // 0..3
    const int src0 = (lane & ~3) | (qc >> 1);
    const int src1 = src0 + 2;
    const bool odd = (qc & 1) != 0;

    // ---- Q A-fragments from permuted smem: 4 LDS.128 per tile ----
    // aq0[t][0..7] = Q[m0+qr][cols qc+4j], aq1 same for row +8
    unsigned aq0[MT][8], aq1[MT][8];
    #pragma unroll
    for (int t = 0; t < MT; t++) {
        const unsigned* r0 = Qp + (m0base + t * 16 + qr) * STRQ + qc * 8;
        const unsigned* r1 = r0 + 8 * STRQ;
        *(uint4*)(&aq0[t][0]) = *(const uint4*)(r0);
        *(uint4*)(&aq0[t][4]) = *(const uint4*)(r0 + 4);
        *(uint4*)(&aq1[t][0]) = *(const uint4*)(r1);
        *(uint4*)(&aq1[t][4]) = *(const uint4*)(r1 + 4);
    }

    float o[MT][4][4];
    float l0[MT], l1[MT];
    const float* mr0[MT];
    #pragma unroll
    for (int t = 0; t < MT; t++) {
        l0[t] = 0.f; l1[t] = 0.f;
        mr0[t] = mbase + (m0base + t * 16 + qr) * NSEQ + 2 * qc;
        #pragma unroll
        for (int dt = 0; dt < 4; dt++) {
            o[t][dt][0] = 0.f; o[t][dt][1] = 0.f;
            o[t][dt][2] = 0.f; o[t][dt][3] = 0.f;
        }
    }

    // ---- stream over 144 key cols: 6 chunks x 3 n-tiles ----
    #pragma unroll
    for (int ch = 0; ch < 6; ch++) {
        float acc[MT][3][4];

        // S = Q @ K^T (+mask): K frags loaded ONCE per n-tile, reused by all MT tiles
        #pragma unroll
        for (int j = 0; j < 3; j++) {
            const int n0 = (ch * 3 + j) * 8;
            const uint4 B  = *(const uint4*)(Kp + (n0 + qr) * STRQ + qc * 8);
            const uint4 Bb = *(const uint4*)(Kp + (n0 + qr) * STRQ + qc * 8 + 4);
            #pragma unroll
            for (int t = 0; t < MT; t++) {
                float* a = acc[t][j];
                a[0] = 0.f; a[1] = 0.f; a[2] = 0.f; a[3] = 0.f;
                mma_tf32(a, aq0[t][0], aq1[t][0], aq0[t][1], aq1[t][1], B.x,  B.y);
                mma_tf32(a, aq0[t][2], aq1[t][2], aq0[t][3], aq1[t][3], B.z,  B.w);
                mma_tf32(a, aq0[t][4], aq1[t][4], aq0[t][5], aq1[t][5], Bb.x, Bb.y);
                mma_tf32(a, aq0[t][6], aq1[t][6], aq0[t][7], aq1[t][7], Bb.z, Bb.w);
                const float2 mv0 = *(const float2*)(mr0[t] + n0);
                const float2 mv1 = *(const float2*)(mr0[t] + 8 * NSEQ + n0);
                a[0] += mv0.x; a[1] += mv0.y;
                a[2] += mv1.x; a[3] += mv1.y;
            }
        }

        // P = exp(S); accumulate row sums
        #pragma unroll
        for (int j = 0; j < 3; j++) {
            #pragma unroll
            for (int t = 0; t < MT; t++) {
                float* a = acc[t][j];
                a[0] = __expf(a[0]); a[1] = __expf(a[1]);
                a[2] = __expf(a[2]); a[3] = __expf(a[3]);
                l0[t] += a[0] + a[1];
                l1[t] += a[2] + a[3];
            }
        }

        // O += P @ V: V frags loaded ONCE per k-tile, reused by all MT tiles
        #pragma unroll
        for (int j = 0; j < 3; j++) {
            const int krow = (ch * 3 + j) * 8;
            const uint4 Vl = *(const uint4*)(Vp + (krow + qc    ) * STRV + qr * 4);
            const uint4 Vh = *(const uint4*)(Vp + (krow + qc + 4) * STRV + qr * 4);
            #pragma unroll
            for (int t = 0; t < MT; t++) {
                const float* a = acc[t][j];
                const float s00 = __shfl_sync(FULLM, a[0], src0);
                const float s01 = __shfl_sync(FULLM, a[1], src0);
                const float s10 = __shfl_sync(FULLM, a[2], src0);
                const float s11 = __shfl_sync(FULLM, a[3], src0);
                const float t00 = __shfl_sync(FULLM, a[0], src1);
                const float t01 = __shfl_sync(FULLM, a[1], src1);
                const float t10 = __shfl_sync(FULLM, a[2], src1);
                const float t11 = __shfl_sync(FULLM, a[3], src1);
                const unsigned pa0 = f2tf32(odd ? s01 : s00);
                const unsigned pa1 = f2tf32(odd ? s11 : s10);
                const unsigned pa2 = f2tf32(odd ? t01 : t00);
                const unsigned pa3 = f2tf32(odd ? t11 : t10);
                mma_tf32(o[t][0], pa0, pa1, pa2, pa3, Vl.x, Vh.x);
                mma_tf32(o[t][1], pa0, pa1, pa2, pa3, Vl.y, Vh.y);
                mma_tf32(o[t][2], pa0, pa1, pa2, pa3, Vl.z, Vh.z);
                mma_tf32(o[t][3], pa0, pa1, pa2, pa3, Vl.w, Vh.w);
            }
        }
    }

    // ---- normalize + store ----
    #pragma unroll
    for (int t = 0; t < MT; t++) {
        float a0 = l0[t], a1 = l1[t];
        a0 += __shfl_xor_sync(FULLM, a0, 1);
        a0 += __shfl_xor_sync(FULLM, a0, 2);
        a1 += __shfl_xor_sync(FULLM, a1, 1);
        a1 += __shfl_xor_sync(FULLM, a1, 2);
        const float i0 = 1.f / a0;
        const float i1 = 1.f / a1;
        const int m0 = m0base + t * 16;
        #pragma unroll
        for (int dt = 0; dt < 4; dt++) {
            const int d = dt * 8 + 2 * qc;
            float2* p0 = (float2*)(obase + (m0 + qr    ) * 128 + d);
            float2* p1 = (float2*)(obase + (m0 + qr + 8) * 128 + d);
            *p0 = make_float2(o[t][dt][0] * i0, o[t][dt][1] * i0);
            *p1 = make_float2(o[t][dt][2] * i1, o[t][dt][3] * i1);
        }
    }
}

__global__ void __launch_bounds__(160, 3)
attn_kernel(const float* __restrict__ qkv,
            const float* __restrict__ mask,
            float* __restrict__ out)
{
    extern __shared__ unsigned sm[];
    unsigned* Qp = sm;                     // perm: orig col c -> i = (c%4)*8 + c/4
    unsigned* Kp = sm + QK_ELEMS;          // same perm
    unsigned* Vp = sm + 2 * QK_ELEMS;      // perm: orig col c -> i = (c%8)*4 + c/8

    const int bh = blockIdx.x;
    const int b = bh >> 2;
    const int h = bh & 3;
    const int tid = threadIdx.x;

    // ---- Stage Q (pre-scaled), K, V into smem as tf32, fragment-permuted ----
    const float* gbase = qkv + (size_t)b * (NSEQ * 384) + h * 32;
    for (int idx = tid; idx < NSEQ * 8; idx += 160) {
        const int row = idx >> 3;
        const int c4  = (idx & 7) << 2;
        const float* g = gbase + row * 384 + c4;
        float4 q = *(const float4*)(g);
        float4 k = *(const float4*)(g + 128);
        float4 v = *(const float4*)(g + 256);
        unsigned* qr_ = Qp + row * STRQ + (c4 >> 2);
        qr_[0]  = f2tf32(q.x * SCALE_F);
        qr_[8]  = f2tf32(q.y * SCALE_F);
        qr_[16] = f2tf32(q.z * SCALE_F);
        qr_[24] = f2tf32(q.w * SCALE_F);
        unsigned* kr_ = Kp + row * STRQ + (c4 >> 2);
        kr_[0]  = f2tf32(k.x);
        kr_[8]  = f2tf32(k.y);
        kr_[16] = f2tf32(k.z);
        kr_[24] = f2tf32(k.w);
        unsigned* vr_ = Vp + row * STRV + ((c4 & 7) << 2) + (c4 >> 3);
        vr_[0]  = f2tf32(v.x);
        vr_[4]  = f2tf32(v.y);
        vr_[8]  = f2tf32(v.z);
        vr_[12] = f2tf32(v.w);
    }
    __syncthreads();

    const int warp = tid >> 5;    // 0..4
    const int lane = tid & 31;

    const float* mbase = mask + h * (NSEQ * NSEQ);
    float* obase = out + (size_t)b * (NSEQ * 128) + h * 32;

    if (warp < 4) {
        attn_warp_body<2>(Qp, Kp, Vp, mbase, obase, warp * 32, lane);
    } else {
        attn_warp_body<1>(Qp, Kp, Vp, mbase, obase, 128, lane);
    }
}

extern "C" void kernel_launch(void* const* d_in, const int* in_sizes, int n_in,
                              void* d_out, int out_size)
{
    const float* qkv  = (const float*)d_in[0];
    const float* mask = (const float*)d_in[1];
    float* out = (float*)d_out;

    cudaFuncSetAttribute(attn_kernel,
                         cudaFuncAttributeMaxDynamicSharedMemorySize, SMEM_BYTES);
    attn_kernel<<<2048 * 4, 160, SMEM_BYTES>>>(qkv, mask, out);
}

// round 10
// speedup vs baseline: 1.5119x; 1.4571x over previous
#include <cuda_runtime.h>
#include <cuda_fp16.h>
#include <cstdint>
#include <cstddef>

// Batched MHA: qkv [2048,144,384] f32, mask [1,4,144,144] f32 -> out [2048,144,128] f32
// B=2048, H=4, N=144, d=32. One CTA per (b,h); 288 threads = 9 warps, one m16 tile each
// (the R3 skeleton), but fp16 m16n8k16 mma: half the mma count, half the operand LDS,
// V via ldmatrix.trans, and ZERO shuffles (fp16 S C-frag == PV A-frag layout).
// One-pass softmax, exp(S-4) guard keeps P finite in fp16 (scores max ~ +9).

#define SCALE_F 0.17677669529663687f
#define L2E 1.4426950408889634f

__device__ __forceinline__ void mma_f16(float* d,
    unsigned a0, unsigned a1, unsigned a2, unsigned a3,
    unsigned b0, unsigned b1)
{
    asm volatile(
        "mma.sync.aligned.m16n8k16.row.col.f32.f16.f16.f32 "
        "{%0,%1,%2,%3},{%4,%5,%6,%7},{%8,%9},{%0,%1,%2,%3};"
        : "+f"(d[0]), "+f"(d[1]), "+f"(d[2]), "+f"(d[3])
        : "r"(a0), "r"(a1), "r"(a2), "r"(a3), "r"(b0), "r"(b1));
}

// pack half2: lo = first element (lower k index), hi = second
__device__ __forceinline__ unsigned pack_h2(float lo, float hi) {
    unsigned r;
    asm("cvt.rn.f16x2.f32 %0, %1, %2;" : "=r"(r) : "f"(hi), "f"(lo));
    return r;
}

// exp(x - 4) via single FFMA + MUFU.EX2
__device__ __forceinline__ float exp4(float x) {
    float r;
    asm("ex2.approx.f32 %0, %1;" : "=f"(r) : "f"(fmaf(x, L2E, -4.0f * L2E)));
    return r;
}

__device__ __forceinline__ void ldsm4t(unsigned& r0, unsigned& r1,
                                       unsigned& r2, unsigned& r3, unsigned addr) {
    asm volatile(
        "ldmatrix.sync.aligned.m8n8.x4.trans.shared.b16 {%0,%1,%2,%3}, [%4];"
        : "=r"(r0), "=r"(r1), "=r"(r2), "=r"(r3) : "r"(addr));
}

constexpr int NSEQ  = 144;
constexpr int QKSTR = 32;                       // halves per Q/K row (no pad needed)
constexpr int VSTR  = 40;                       // halves per V row (pad for LDSM banks)
constexpr int K_OFF = NSEQ * QKSTR;             // 4608 halves
constexpr int V_OFF = 2 * NSEQ * QKSTR;         // 9216 halves
constexpr int SMEM_BYTES = (2 * NSEQ * QKSTR + NSEQ * VSTR) * 2;   // 29952 B

__global__ void __launch_bounds__(288, 2)
attn_kernel(const float* __restrict__ qkv,
            const float* __restrict__ mask,
            float* __restrict__ out)
{
    extern __shared__ __half sh[];
    __half* Qh = sh;                 // perm: d -> pos = ((d&7)>>1)*8 + (d>>3)*2 + (d&1)
    __half* Kh = sh + K_OFF;         // same perm
    __half* Vh = sh + V_OFF;         // plain row-major [key][d], stride VSTR

    const int bh = blockIdx.x;
    const int b = bh >> 2;
    const int h = bh & 3;
    const int tid = threadIdx.x;

    // ---- Stage Q (pre-scaled), K (both fragment-permuted) and V (plain) as fp16 ----
    const float* gbase = qkv + (size_t)b * (NSEQ * 384) + h * 32;
    for (int idx = tid; idx < NSEQ * 8; idx += 288) {
        const int row = idx >> 3;
        const int c4  = (idx & 7) << 2;
        const float* g = gbase + row * 384 + c4;
        float4 q = *(const float4*)(g);
        float4 k = *(const float4*)(g + 128);
        float4 v = *(const float4*)(g + 256);
        const int pos = ((c4 & 7) >> 1) * 8 + ((c4 >> 3) << 1);
        *(__half2*)(Qh + row * QKSTR + pos)     = __floats2half2_rn(q.x * SCALE_F, q.y * SCALE_F);
        *(__half2*)(Qh + row * QKSTR + pos + 8) = __floats2half2_rn(q.z * SCALE_F, q.w * SCALE_F);
        *(__half2*)(Kh + row * QKSTR + pos)     = __floats2half2_rn(k.x, k.y);
        *(__half2*)(Kh + row * QKSTR + pos + 8) = __floats2half2_rn(k.z, k.w);
        *(__half2*)(Vh + row * VSTR + c4)       = __floats2half2_rn(v.x, v.y);
        *(__half2*)(Vh + row * VSTR + c4 + 2)   = __floats2half2_rn(v.z, v.w);
    }
    __syncthreads();

    const int warp = tid >> 5;       // 0..8 -> m-tile
    const int lane = tid & 31;
    const int qr = lane >> 2;        // 0..7
    const int qc = lane & 3;         // 0..3
    const int m0 = warp * 16;

    // ---- Q A-fragments: ONE LDS.128 per row covers all 32 d ----
    // .x = (d 2qc,2qc+1) .y = (8+2qc pr) .z = (16+2qc pr) .w = (24+2qc pr)
    const uint4 A0 = *(const uint4*)(Qh + (m0 + qr    ) * QKSTR + qc * 8);
    const uint4 A1 = *(const uint4*)(Qh + (m0 + qr + 8) * QKSTR + qc * 8);

    // ---- V ldmatrix lane base: blk = lane>>3, rowi = lane&7 ----
    // block b: keys 16t + (b&1)*8 + rowi, d base (b>>1)*8 (+ dp*16)
    const unsigned vu = (unsigned)__cvta_generic_to_shared(Vh);
    const int blk = lane >> 3;
    const int rowi = lane & 7;
    const unsigned vbase = vu + (((blk & 1) * 8 + rowi) * VSTR + (blk >> 1) * 8) * 2;

    const float* mr0 = mask + h * (NSEQ * NSEQ) + (m0 + qr) * NSEQ + 2 * qc;
    const float* mr1 = mr0 + 8 * NSEQ;
    float* obase = out + (size_t)b * (NSEQ * 128) + h * 32;

    float o[4][4];
    #pragma unroll
    for (int dt = 0; dt < 4; dt++) {
        o[dt][0] = 0.f; o[dt][1] = 0.f; o[dt][2] = 0.f; o[dt][3] = 0.f;
    }
    float l0 = 0.f, l1 = 0.f;

    // ---- stream over 144 key cols: 3 chunks x 6 n-tiles (= 3 k16-tiles for PV) ----
    #pragma unroll
    for (int ch = 0; ch < 3; ch++) {
        float acc[6][4];

        // S = Q @ K^T (+mask): one LDS.128 per n-tile, two mmas
        #pragma unroll
        for (int j = 0; j < 6; j++) {
            const int n0 = (ch * 6 + j) * 8;
            const uint4 B = *(const uint4*)(Kh + (n0 + qr) * QKSTR + qc * 8);
            float* a = acc[j];
            a[0] = 0.f; a[1] = 0.f; a[2] = 0.f; a[3] = 0.f;
            mma_f16(a, A0.x, A1.x, A0.y, A1.y, B.x, B.y);   // d 0..15
            mma_f16(a, A0.z, A1.z, A0.w, A1.w, B.z, B.w);   // d 16..31
            const float2 mv0 = *(const float2*)(mr0 + n0);
            const float2 mv1 = *(const float2*)(mr1 + n0);
            a[0] += mv0.x; a[1] += mv0.y;
            a[2] += mv1.x; a[3] += mv1.y;
        }

        // P = exp(S - 4) (guard for fp16 range; ratio unchanged); row sums in f32
        #pragma unroll
        for (int j = 0; j < 6; j++) {
            float* a = acc[j];
            a[0] = exp4(a[0]); a[1] = exp4(a[1]);
            a[2] = exp4(a[2]); a[3] = exp4(a[3]);
            l0 += a[0] + a[1];
            l1 += a[2] + a[3];
        }

        // O += P @ V: fp16 C-frag IS the A-frag layout -> just pack, no shfl.
        #pragma unroll
        for (int u = 0; u < 3; u++) {
            const int t = ch * 3 + u;
            const unsigned a0 = pack_h2(acc[2*u  ][0], acc[2*u  ][1]);  // row qr,   keys 16t+2qc,+1
            const unsigned a1 = pack_h2(acc[2*u  ][2], acc[2*u  ][3]);  // row qr+8
            const unsigned a2 = pack_h2(acc[2*u+1][0], acc[2*u+1][1]);  // row qr,   keys +8
            const unsigned a3 = pack_h2(acc[2*u+1][2], acc[2*u+1][3]);
            const unsigned addr = vbase + t * (16 * VSTR * 2);
            unsigned vb0, vb1, vb2, vb3, vb4, vb5, vb6, vb7;
            ldsm4t(vb0, vb1, vb2, vb3, addr);        // d 0..15   (dt 0,1)
            ldsm4t(vb4, vb5, vb6, vb7, addr + 32);   // d 16..31  (dt 2,3)
            mma_f16(o[0], a0, a1, a2, a3, vb0, vb1);
            mma_f16(o[1], a0, a1, a2, a3, vb2, vb3);
            mma_f16(o[2], a0, a1, a2, a3, vb4, vb5);
            mma_f16(o[3], a0, a1, a2, a3, vb6, vb7);
        }
    }

    // ---- normalize (quad reductions) + store ----
    l0 += __shfl_xor_sync(0xffffffffu, l0, 1);
    l0 += __shfl_xor_sync(0xffffffffu, l0, 2);
    l1 += __shfl_xor_sync(0xffffffffu, l1, 1);
    l1 += __shfl_xor_sync(0xffffffffu, l1, 2);
    const float i0 = 1.f / l0;
    const float i1 = 1.f / l1;

    #pragma unroll
    for (int dt = 0; dt < 4; dt++) {
        const int d = dt * 8 + 2 * qc;
        float2* p0 = (float2*)(obase + (m0 + qr    ) * 128 + d);
        float2* p1 = (float2*)(obase + (m0 + qr + 8) * 128 + d);
        *p0 = make_float2(o[dt][0] * i0, o[dt][1] * i0);
        *p1 = make_float2(o[dt][2] * i1, o[dt][3] * i1);
    }
}

extern "C" void kernel_launch(void* const* d_in, const int* in_sizes, int n_in,
                              void* d_out, int out_size)
{
    const float* qkv  = (const float*)d_in[0];
    const float* mask = (const float*)d_in[1];
    float* out = (float*)d_out;

    cudaFuncSetAttribute(attn_kernel,
                         cudaFuncAttributeMaxDynamicSharedMemorySize, SMEM_BYTES);
    attn_kernel<<<2048 * 4, 288, SMEM_BYTES>>>(qkv, mask, out);
}

// round 11
// speedup vs baseline: 1.7245x; 1.1406x over previous
#include <cuda_runtime.h>
#include <cuda_fp16.h>
#include <cstdint>
#include <cstddef>

// Batched MHA: qkv [2048,144,384] f32, mask [1,4,144,144] f32 -> out [2048,144,128] f32
// B=2048, H=4, N=144, d=32. One CTA per (b,h); 288 threads = 9 warps, one m16 tile each.
// fp16 m16n8k16 mma; V via ldmatrix.trans; zero shuffles (S C-frag == PV A-frag).
// NEW: mask is pre-permuted into mma-fragment order by a tiny pre-kernel so every
// mask fetch in the hot kernel is ONE coalesced LDG.128 (4 L1 wavefronts) instead of
// a scattered LDG.64 touching 8 lines (8 wavefronts). Mask was the dominant L1 term.

#define SCALE_F 0.17677669529663687f
#define L2E 1.4426950408889634f

__device__ __forceinline__ void mma_f16(float* d,
    unsigned a0, unsigned a1, unsigned a2, unsigned a3,
    unsigned b0, unsigned b1)
{
    asm volatile(
        "mma.sync.aligned.m16n8k16.row.col.f32.f16.f16.f32 "
        "{%0,%1,%2,%3},{%4,%5,%6,%7},{%8,%9},{%0,%1,%2,%3};"
        : "+f"(d[0]), "+f"(d[1]), "+f"(d[2]), "+f"(d[3])
        : "r"(a0), "r"(a1), "r"(a2), "r"(a3), "r"(b0), "r"(b1));
}

__device__ __forceinline__ unsigned pack_h2(float lo, float hi) {
    unsigned r;
    asm("cvt.rn.f16x2.f32 %0, %1, %2;" : "=r"(r) : "f"(hi), "f"(lo));
    return r;
}

// exp(x - 4) via FFMA + MUFU.EX2 (fp16-range guard; softmax ratio unchanged)
__device__ __forceinline__ float exp4(float x) {
    float r;
    asm("ex2.approx.f32 %0, %1;" : "=f"(r) : "f"(fmaf(x, L2E, -4.0f * L2E)));
    return r;
}

__device__ __forceinline__ void ldsm4t(unsigned& r0, unsigned& r1,
                                       unsigned& r2, unsigned& r3, unsigned addr) {
    asm volatile(
        "ldmatrix.sync.aligned.m8n8.x4.trans.shared.b16 {%0,%1,%2,%3}, [%4];"
        : "=r"(r0), "=r"(r1), "=r"(r2), "=r"(r3) : "r"(addr));
}

constexpr int NSEQ  = 144;
constexpr int QKSTR = 32;                       // halves per Q/K row
constexpr int VSTR  = 40;                       // halves per V row (LDSM bank pad)
constexpr int K_OFF = NSEQ * QKSTR;
constexpr int V_OFF = 2 * NSEQ * QKSTR;
constexpr int SMEM_BYTES = (2 * NSEQ * QKSTR + NSEQ * VSTR) * 2;   // 29952 B

// Fragment-ordered mask: [h][mtile 9][chunk 3][j 6][lane 32] float4
// float4 = (row qr: col 2qc, 2qc+1, row qr+8: col 2qc, 2qc+1) at n0=(ch*6+j)*8
constexpr int MPERM_ENTRIES = 4 * 9 * 3 * 6 * 32;   // 20736 float4 = 324 KB
__device__ float4 MaskPerm[MPERM_ENTRIES];

__global__ void __launch_bounds__(256)
mask_perm_kernel(const float* __restrict__ mask)
{
    const int idx = blockIdx.x * blockDim.x + threadIdx.x;
    if (idx >= MPERM_ENTRIES) return;
    const int lane = idx & 31;
    const int rest = idx >> 5;          // ((h*9+mt)*3+ch)*6 + j
    const int j  = rest % 6;
    const int ch = (rest / 6) % 3;
    const int mt = (rest / 18) % 9;
    const int h  = rest / 162;
    const int qr = lane >> 2;
    const int qc = lane & 3;
    const int r = mt * 16 + qr;
    const int c = (ch * 6 + j) * 8 + 2 * qc;
    const float* mb = mask + ((size_t)h * NSEQ + r) * NSEQ + c;
    MaskPerm[idx] = make_float4(mb[0], mb[1], mb[8 * NSEQ], mb[8 * NSEQ + 1]);
}

__global__ void __launch_bounds__(288, 2)
attn_kernel(const float* __restrict__ qkv,
            float* __restrict__ out)
{
    extern __shared__ __half sh[];
    __half* Qh = sh;                 // perm: d -> pos = ((d&7)>>1)*8 + (d>>3)*2 + (d&1)
    __half* Kh = sh + K_OFF;         // same perm
    __half* Vh = sh + V_OFF;         // plain row-major [key][d], stride VSTR

    const int bh = blockIdx.x;
    const int b = bh >> 2;
    const int h = bh & 3;
    const int tid = threadIdx.x;

    // ---- Stage Q (pre-scaled), K (fragment-permuted) and V (plain) as fp16 ----
    const float* gbase = qkv + (size_t)b * (NSEQ * 384) + h * 32;
    for (int idx = tid; idx < NSEQ * 8; idx += 288) {
        const int row = idx >> 3;
        const int c4  = (idx & 7) << 2;
        const float* g = gbase + row * 384 + c4;
        float4 q = *(const float4*)(g);
        float4 k = *(const float4*)(g + 128);
        float4 v = *(const float4*)(g + 256);
        const int pos = ((c4 & 7) >> 1) * 8 + ((c4 >> 3) << 1);
        *(__half2*)(Qh + row * QKSTR + pos)     = __floats2half2_rn(q.x * SCALE_F, q.y * SCALE_F);
        *(__half2*)(Qh + row * QKSTR + pos + 8) = __floats2half2_rn(q.z * SCALE_F, q.w * SCALE_F);
        *(__half2*)(Kh + row * QKSTR + pos)     = __floats2half2_rn(k.x, k.y);
        *(__half2*)(Kh + row * QKSTR + pos + 8) = __floats2half2_rn(k.z, k.w);
        *(__half2*)(Vh + row * VSTR + c4)       = __floats2half2_rn(v.x, v.y);
        *(__half2*)(Vh + row * VSTR + c4 + 2)   = __floats2half2_rn(v.z, v.w);
    }
    __syncthreads();

    const int warp = tid >> 5;       // 0..8 -> m-tile
    const int lane = tid & 31;
    const int qr = lane >> 2;
    const int qc = lane & 3;
    const int m0 = warp * 16;

    // ---- Q A-fragments: ONE LDS.128 per row covers all 32 d ----
    const uint4 A0 = *(const uint4*)(Qh + (m0 + qr    ) * QKSTR + qc * 8);
    const uint4 A1 = *(const uint4*)(Qh + (m0 + qr + 8) * QKSTR + qc * 8);

    // ---- V ldmatrix lane base ----
    const unsigned vu = (unsigned)__cvta_generic_to_shared(Vh);
    const int blk = lane >> 3;
    const int rowi = lane & 7;
    const unsigned vbase = vu + (((blk & 1) * 8 + rowi) * VSTR + (blk >> 1) * 8) * 2;

    // ---- fragment-ordered mask pointer for this warp ----
    const float4* mp = MaskPerm + ((h * 9 + warp) * 3) * 6 * 32 + lane;

    float* obase = out + (size_t)b * (NSEQ * 128) + h * 32;

    float o[4][4];
    #pragma unroll
    for (int dt = 0; dt < 4; dt++) {
        o[dt][0] = 0.f; o[dt][1] = 0.f; o[dt][2] = 0.f; o[dt][3] = 0.f;
    }
    float l0 = 0.f, l1 = 0.f;

    // ---- stream over 144 key cols: 3 chunks x 6 n-tiles ----
    #pragma unroll
    for (int ch = 0; ch < 3; ch++) {
        float acc[6][4];

        // S = Q @ K^T (+mask): mask = one coalesced LDG.128 per n-tile
        #pragma unroll
        for (int j = 0; j < 6; j++) {
            const int n0 = (ch * 6 + j) * 8;
            const float4 mv = mp[(ch * 6 + j) * 32];        // issue early: overlaps mma
            const uint4 B = *(const uint4*)(Kh + (n0 + qr) * QKSTR + qc * 8);
            float* a = acc[j];
            a[0] = 0.f; a[1] = 0.f; a[2] = 0.f; a[3] = 0.f;
            mma_f16(a, A0.x, A1.x, A0.y, A1.y, B.x, B.y);   // d 0..15
            mma_f16(a, A0.z, A1.z, A0.w, A1.w, B.z, B.w);   // d 16..31
            a[0] += mv.x; a[1] += mv.y;
            a[2] += mv.z; a[3] += mv.w;
        }

        // P = exp(S - 4); row sums in f32
        #pragma unroll
        for (int j = 0; j < 6; j++) {
            float* a = acc[j];
            a[0] = exp4(a[0]); a[1] = exp4(a[1]);
            a[2] = exp4(a[2]); a[3] = exp4(a[3]);
            l0 += a[0] + a[1];
            l1 += a[2] + a[3];
        }

        // O += P @ V: fp16 C-frag IS the A-frag layout -> pack only, no shfl
        #pragma unroll
        for (int u = 0; u < 3; u++) {
            const int t = ch * 3 + u;
            const unsigned a0 = pack_h2(acc[2*u  ][0], acc[2*u  ][1]);
            const unsigned a1 = pack_h2(acc[2*u  ][2], acc[2*u  ][3]);
            const unsigned a2 = pack_h2(acc[2*u+1][0], acc[2*u+1][1]);
            const unsigned a3 = pack_h2(acc[2*u+1][2], acc[2*u+1][3]);
            const unsigned addr = vbase + t * (16 * VSTR * 2);
            unsigned vb0, vb1, vb2, vb3, vb4, vb5, vb6, vb7;
            ldsm4t(vb0, vb1, vb2, vb3, addr);        // d 0..15
            ldsm4t(vb4, vb5, vb6, vb7, addr + 32);   // d 16..31
            mma_f16(o[0], a0, a1, a2, a3, vb0, vb1);
            mma_f16(o[1], a0, a1, a2, a3, vb2, vb3);
            mma_f16(o[2], a0, a1, a2, a3, vb4, vb5);
            mma_f16(o[3], a0, a1, a2, a3, vb6, vb7);
        }
    }

    // ---- normalize (quad reductions) + store ----
    l0 += __shfl_xor_sync(0xffffffffu, l0, 1);
    l0 += __shfl_xor_sync(0xffffffffu, l0, 2);
    l1 += __shfl_xor_sync(0xffffffffu, l1, 1);
    l1 += __shfl_xor_sync(0xffffffffu, l1, 2);
    const float i0 = 1.f / l0;
    const float i1 = 1.f / l1;

    #pragma unroll
    for (int dt = 0; dt < 4; dt++) {
        const int d = dt * 8 + 2 * qc;
        float2* p0 = (float2*)(obase + (m0 + qr    ) * 128 + d);
        float2* p1 = (float2*)(obase + (m0 + qr + 8) * 128 + d);
        *p0 = make_float2(o[dt][0] * i0, o[dt][1] * i0);
        *p1 = make_float2(o[dt][2] * i1, o[dt][3] * i1);
    }
}

extern "C" void kernel_launch(void* const* d_in, const int* in_sizes, int n_in,
                              void* d_out, int out_size)
{
    const float* qkv  = (const float*)d_in[0];
    const float* mask = (const float*)d_in[1];
    float* out = (float*)d_out;

    mask_perm_kernel<<<(MPERM_ENTRIES + 255) / 256, 256>>>(mask);

    cudaFuncSetAttribute(attn_kernel,
                         cudaFuncAttributeMaxDynamicSharedMemorySize, SMEM_BYTES);
    attn_kernel<<<2048 * 4, 288, SMEM_BYTES>>>(qkv, out);
}

// round 12
// speedup vs baseline: 2.0557x; 1.1921x over previous
#include <cuda_runtime.h>
#include <cuda_fp16.h>
#include <cstdint>
#include <cstddef>

// Batched MHA: qkv [2048,144,384] f32, mask [1,4,144,144] f32 -> out [2048,144,128] f32
// B=2048, H=4, N=144, d=32. One CTA per (b,h); 288 threads = 9 warps, one m16 tile each.
// fp16 m16n8k16 mma; V via ldmatrix.trans; zero shuffles; mask pre-permuted to
// fragment order (one coalesced LDG.128 per n-tile).
// NEW vs R11: 9 chunks x 2 n-tiles (acc = 8 regs instead of 24) + launch_bounds(288,3)
// -> <=75 regs -> 3 CTAs/SM -> 27 warps/SM (42% occ) for latency hiding.

#define SCALE_F 0.17677669529663687f
#define L2E 1.4426950408889634f

__device__ __forceinline__ void mma_f16(float* d,
    unsigned a0, unsigned a1, unsigned a2, unsigned a3,
    unsigned b0, unsigned b1)
{
    asm volatile(
        "mma.sync.aligned.m16n8k16.row.col.f32.f16.f16.f32 "
        "{%0,%1,%2,%3},{%4,%5,%6,%7},{%8,%9},{%0,%1,%2,%3};"
        : "+f"(d[0]), "+f"(d[1]), "+f"(d[2]), "+f"(d[3])
        : "r"(a0), "r"(a1), "r"(a2), "r"(a3), "r"(b0), "r"(b1));
}

__device__ __forceinline__ unsigned pack_h2(float lo, float hi) {
    unsigned r;
    asm("cvt.rn.f16x2.f32 %0, %1, %2;" : "=r"(r) : "f"(hi), "f"(lo));
    return r;
}

// exp(x - 4) via FFMA + MUFU.EX2 (fp16-range guard; softmax ratio unchanged)
__device__ __forceinline__ float exp4(float x) {
    float r;
    asm("ex2.approx.f32 %0, %1;" : "=f"(r) : "f"(fmaf(x, L2E, -4.0f * L2E)));
    return r;
}

__device__ __forceinline__ void ldsm4t(unsigned& r0, unsigned& r1,
                                       unsigned& r2, unsigned& r3, unsigned addr) {
    asm volatile(
        "ldmatrix.sync.aligned.m8n8.x4.trans.shared.b16 {%0,%1,%2,%3}, [%4];"
        : "=r"(r0), "=r"(r1), "=r"(r2), "=r"(r3) : "r"(addr));
}

constexpr int NSEQ  = 144;
constexpr int QKSTR = 32;                       // halves per Q/K row
constexpr int VSTR  = 40;                       // halves per V row (LDSM bank pad)
constexpr int K_OFF = NSEQ * QKSTR;
constexpr int V_OFF = 2 * NSEQ * QKSTR;
constexpr int SMEM_BYTES = (2 * NSEQ * QKSTR + NSEQ * VSTR) * 2;   // 29952 B

// Fragment-ordered mask: [h][mtile 9][ntile 18][lane 32] float4
// float4 = (row qr: col 2qc, 2qc+1, row qr+8: col 2qc, 2qc+1) at n0 = ntile*8
constexpr int MPERM_ENTRIES = 4 * 9 * 18 * 32;   // 20736 float4 = 324 KB
__device__ float4 MaskPerm[MPERM_ENTRIES];

__global__ void __launch_bounds__(256)
mask_perm_kernel(const float* __restrict__ mask)
{
    const int idx = blockIdx.x * blockDim.x + threadIdx.x;
    if (idx >= MPERM_ENTRIES) return;
    const int lane = idx & 31;
    const int rest = idx >> 5;          // (h*9+mt)*18 + nt
    const int nt = rest % 18;
    const int mt = (rest / 18) % 9;
    const int h  = rest / 162;
    const int qr = lane >> 2;
    const int qc = lane & 3;
    const int r = mt * 16 + qr;
    const int c = nt * 8 + 2 * qc;
    const float* mb = mask + ((size_t)h * NSEQ + r) * NSEQ + c;
    MaskPerm[idx] = make_float4(mb[0], mb[1], mb[8 * NSEQ], mb[8 * NSEQ + 1]);
}

__global__ void __launch_bounds__(288, 3)
attn_kernel(const float* __restrict__ qkv,
            float* __restrict__ out)
{
    extern __shared__ __half sh[];
    __half* Qh = sh;                 // perm: d -> pos = ((d&7)>>1)*8 + (d>>3)*2 + (d&1)
    __half* Kh = sh + K_OFF;         // same perm
    __half* Vh = sh + V_OFF;         // plain row-major [key][d], stride VSTR

    const int bh = blockIdx.x;
    const int b = bh >> 2;
    const int h = bh & 3;
    const int tid = threadIdx.x;

    // ---- Stage Q (pre-scaled), K (fragment-permuted) and V (plain) as fp16 ----
    const float* gbase = qkv + (size_t)b * (NSEQ * 384) + h * 32;
    for (int idx = tid; idx < NSEQ * 8; idx += 288) {
        const int row = idx >> 3;
        const int c4  = (idx & 7) << 2;
        const float* g = gbase + row * 384 + c4;
        float4 q = *(const float4*)(g);
        float4 k = *(const float4*)(g + 128);
        float4 v = *(const float4*)(g + 256);
        const int pos = ((c4 & 7) >> 1) * 8 + ((c4 >> 3) << 1);
        *(__half2*)(Qh + row * QKSTR + pos)     = __floats2half2_rn(q.x * SCALE_F, q.y * SCALE_F);
        *(__half2*)(Qh + row * QKSTR + pos + 8) = __floats2half2_rn(q.z * SCALE_F, q.w * SCALE_F);
        *(__half2*)(Kh + row * QKSTR + pos)     = __floats2half2_rn(k.x, k.y);
        *(__half2*)(Kh + row * QKSTR + pos + 8) = __floats2half2_rn(k.z, k.w);
        *(__half2*)(Vh + row * VSTR + c4)       = __floats2half2_rn(v.x, v.y);
        *(__half2*)(Vh + row * VSTR + c4 + 2)   = __floats2half2_rn(v.z, v.w);
    }
    __syncthreads();

    const int warp = tid >> 5;       // 0..8 -> m-tile
    const int lane = tid & 31;
    const int qr = lane >> 2;
    const int qc = lane & 3;
    const int m0 = warp * 16;

    // ---- Q A-fragments: ONE LDS.128 per row covers all 32 d ----
    const uint4 A0 = *(const uint4*)(Qh + (m0 + qr    ) * QKSTR + qc * 8);
    const uint4 A1 = *(const uint4*)(Qh + (m0 + qr + 8) * QKSTR + qc * 8);

    // ---- V ldmatrix lane base ----
    const unsigned vu = (unsigned)__cvta_generic_to_shared(Vh);
    const int blk = lane >> 3;
    const int rowi = lane & 7;
    const unsigned vbase = vu + (((blk & 1) * 8 + rowi) * VSTR + (blk >> 1) * 8) * 2;

    // ---- fragment-ordered mask pointer for this warp ----
    const float4* mp = MaskPerm + (h * 9 + warp) * 18 * 32 + lane;

    float* obase = out + (size_t)b * (NSEQ * 128) + h * 32;

    float o[4][4];
    #pragma unroll
    for (int dt = 0; dt < 4; dt++) {
        o[dt][0] = 0.f; o[dt][1] = 0.f; o[dt][2] = 0.f; o[dt][3] = 0.f;
    }
    float l0 = 0.f, l1 = 0.f;

    // ---- stream over 144 key cols: 9 chunks x 2 n-tiles (1 k16 PV step each) ----
    #pragma unroll
    for (int ch = 0; ch < 9; ch++) {
        float acc[2][4];

        // S = Q @ K^T (+mask): mask = one coalesced LDG.128 per n-tile
        const float4 mv0 = mp[(ch * 2    ) * 32];
        const float4 mv1 = mp[(ch * 2 + 1) * 32];
        #pragma unroll
        for (int j = 0; j < 2; j++) {
            const int n0 = (ch * 2 + j) * 8;
            const uint4 B = *(const uint4*)(Kh + (n0 + qr) * QKSTR + qc * 8);
            float* a = acc[j];
            a[0] = 0.f; a[1] = 0.f; a[2] = 0.f; a[3] = 0.f;
            mma_f16(a, A0.x, A1.x, A0.y, A1.y, B.x, B.y);   // d 0..15
            mma_f16(a, A0.z, A1.z, A0.w, A1.w, B.z, B.w);   // d 16..31
        }
        acc[0][0] += mv0.x; acc[0][1] += mv0.y;
        acc[0][2] += mv0.z; acc[0][3] += mv0.w;
        acc[1][0] += mv1.x; acc[1][1] += mv1.y;
        acc[1][2] += mv1.z; acc[1][3] += mv1.w;

        // P = exp(S - 4); row sums in f32
        #pragma unroll
        for (int j = 0; j < 2; j++) {
            float* a = acc[j];
            a[0] = exp4(a[0]); a[1] = exp4(a[1]);
            a[2] = exp4(a[2]); a[3] = exp4(a[3]);
            l0 += a[0] + a[1];
            l1 += a[2] + a[3];
        }

        // O += P @ V: fp16 C-frag IS the A-frag layout -> pack only, no shfl
        const unsigned pa0 = pack_h2(acc[0][0], acc[0][1]);
        const unsigned pa1 = pack_h2(acc[0][2], acc[0][3]);
        const unsigned pa2 = pack_h2(acc[1][0], acc[1][1]);
        const unsigned pa3 = pack_h2(acc[1][2], acc[1][3]);
        const unsigned addr = vbase + ch * (16 * VSTR * 2);
        unsigned vb0, vb1, vb2, vb3, vb4, vb5, vb6, vb7;
        ldsm4t(vb0, vb1, vb2, vb3, addr);        // d 0..15
        ldsm4t(vb4, vb5, vb6, vb7, addr + 32);   // d 16..31
        mma_f16(o[0], pa0, pa1, pa2, pa3, vb0, vb1);
        mma_f16(o[1], pa0, pa1, pa2, pa3, vb2, vb3);
        mma_f16(o[2], pa0, pa1, pa2, pa3, vb4, vb5);
        mma_f16(o[3], pa0, pa1, pa2, pa3, vb6, vb7);
    }

    // ---- normalize (quad reductions) + store ----
    l0 += __shfl_xor_sync(0xffffffffu, l0, 1);
    l0 += __shfl_xor_sync(0xffffffffu, l0, 2);
    l1 += __shfl_xor_sync(0xffffffffu, l1, 1);
    l1 += __shfl_xor_sync(0xffffffffu, l1, 2);
    const float i0 = 1.f / l0;
    const float i1 = 1.f / l1;

    #pragma unroll
    for (int dt = 0; dt < 4; dt++) {
        const int d = dt * 8 + 2 * qc;
        float2* p0 = (float2*)(obase + (m0 + qr    ) * 128 + d);
        float2* p1 = (float2*)(obase + (m0 + qr + 8) * 128 + d);
        *p0 = make_float2(o[dt][0] * i0, o[dt][1] * i0);
        *p1 = make_float2(o[dt][2] * i1, o[dt][3] * i1);
    }
}

extern "C" void kernel_launch(void* const* d_in, const int* in_sizes, int n_in,
                              void* d_out, int out_size)
{
    const float* qkv  = (const float*)d_in[0];
    const float* mask = (const float*)d_in[1];
    float* out = (float*)d_out;

    mask_perm_kernel<<<(MPERM_ENTRIES + 255) / 256, 256>>>(mask);

    cudaFuncSetAttribute(attn_kernel,
                         cudaFuncAttributeMaxDynamicSharedMemorySize, SMEM_BYTES);
    attn_kernel<<<2048 * 4, 288, SMEM_BYTES>>>(qkv, out);
}

// round 17
// speedup vs baseline: 2.1742x; 1.0576x over previous
#include <cuda_runtime.h>
#include <cuda_fp16.h>
#include <cstdint>
#include <cstddef>

// Batched MHA: qkv [2048,144,384] f32, mask [1,4,144,144] f32 -> out [2048,144,128] f32
// B=2048, H=4, N=144, d=32. One CTA per (b,h); 288 threads = 9 warps, one m16 tile each.
// fp16 m16n8k16 mma; V via ldmatrix.trans; zero shuffles; mask pre-permuted to
// fragment order.
// (Re-run: previous bench attempt hit an infra failure, kernel unmeasured.)
//  - Q pre-scaled by SCALE*log2e and MaskPerm holds mask*log2e - 4*log2e, so the
//    mma accumulator is INITIALIZED from the mask LDG and softmax is a bare ex2
//    (removes 144 fma-pipe ops per warp-tile and the mask temp registers).
//  - V staging is one STS.64.
//  - launch_bounds(288,4): 4 CTAs/SM -> 36 warps/SM for latency hiding.

#define SCALE_F 0.17677669529663687f
#define L2E 1.4426950408889634f

__device__ __forceinline__ void mma_f16(float* d,
    unsigned a0, unsigned a1, unsigned a2, unsigned a3,
    unsigned b0, unsigned b1)
{
    asm volatile(
        "mma.sync.aligned.m16n8k16.row.col.f32.f16.f16.f32 "
        "{%0,%1,%2,%3},{%4,%5,%6,%7},{%8,%9},{%0,%1,%2,%3};"
        : "+f"(d[0]), "+f"(d[1]), "+f"(d[2]), "+f"(d[3])
        : "r"(a0), "r"(a1), "r"(a2), "r"(a3), "r"(b0), "r"(b1));
}

__device__ __forceinline__ unsigned pack_h2(float lo, float hi) {
    unsigned r;
    asm("cvt.rn.f16x2.f32 %0, %1, %2;" : "=r"(r) : "f"(hi), "f"(lo));
    return r;
}

// bare 2^x (all scaling pre-folded into Q and MaskPerm)
__device__ __forceinline__ float ex2f(float x) {
    float r;
    asm("ex2.approx.f32 %0, %1;" : "=f"(r) : "f"(x));
    return r;
}

__device__ __forceinline__ void ldsm4t(unsigned& r0, unsigned& r1,
                                       unsigned& r2, unsigned& r3, unsigned addr) {
    asm volatile(
        "ldmatrix.sync.aligned.m8n8.x4.trans.shared.b16 {%0,%1,%2,%3}, [%4];"
        : "=r"(r0), "=r"(r1), "=r"(r2), "=r"(r3) : "r"(addr));
}

constexpr int NSEQ  = 144;
constexpr int QKSTR = 32;                       // halves per Q/K row
constexpr int VSTR  = 40;                       // halves per V row (LDSM bank pad)
constexpr int K_OFF = NSEQ * QKSTR;
constexpr int V_OFF = 2 * NSEQ * QKSTR;
constexpr int SMEM_BYTES = (2 * NSEQ * QKSTR + NSEQ * VSTR) * 2;   // 29952 B

// Fragment-ordered mask (pre-multiplied by log2e, minus 4*log2e):
// [h][mtile 9][ntile 18][lane 32] float4
// float4 = (row qr: col 2qc, 2qc+1, row qr+8: col 2qc, 2qc+1) at n0 = ntile*8
constexpr int MPERM_ENTRIES = 4 * 9 * 18 * 32;   // 20736 float4 = 324 KB
__device__ float4 MaskPerm[MPERM_ENTRIES];

__global__ void __launch_bounds__(256)
mask_perm_kernel(const float* __restrict__ mask)
{
    const int idx = blockIdx.x * blockDim.x + threadIdx.x;
    if (idx >= MPERM_ENTRIES) return;
    const int lane = idx & 31;
    const int rest = idx >> 5;          // (h*9+mt)*18 + nt
    const int nt = rest % 18;
    const int mt = (rest / 18) % 9;
    const int h  = rest / 162;
    const int qr = lane >> 2;
    const int qc = lane & 3;
    const int r = mt * 16 + qr;
    const int c = nt * 8 + 2 * qc;
    const float* mb = mask + ((size_t)h * NSEQ + r) * NSEQ + c;
    const float bias = -4.0f * L2E;
    MaskPerm[idx] = make_float4(fmaf(mb[0], L2E, bias),
                                fmaf(mb[1], L2E, bias),
                                fmaf(mb[8 * NSEQ], L2E, bias),
                                fmaf(mb[8 * NSEQ + 1], L2E, bias));
}

__global__ void __launch_bounds__(288, 4)
attn_kernel(const float* __restrict__ qkv,
            float* __restrict__ out)
{
    extern __shared__ __half sh[];
    __half* Qh = sh;                 // perm: d -> pos = ((d&7)>>1)*8 + (d>>3)*2 + (d&1)
    __half* Kh = sh + K_OFF;         // same perm
    __half* Vh = sh + V_OFF;         // plain row-major [key][d], stride VSTR

    const int bh = blockIdx.x;
    const int b = bh >> 2;
    const int h = bh & 3;
    const int tid = threadIdx.x;

    // ---- Stage Q (pre-scaled by SCALE*log2e), K (fragment-permuted), V (plain) ----
    const float* gbase = qkv + (size_t)b * (NSEQ * 384) + h * 32;
    const float QS = SCALE_F * L2E;
    for (int idx = tid; idx < NSEQ * 8; idx += 288) {
        const int row = idx >> 3;
        const int c4  = (idx & 7) << 2;
        const float* g = gbase + row * 384 + c4;
        float4 q = *(const float4*)(g);
        float4 k = *(const float4*)(g + 128);
        float4 v = *(const float4*)(g + 256);
        const int pos = ((c4 & 7) >> 1) * 8 + ((c4 >> 3) << 1);
        *(__half2*)(Qh + row * QKSTR + pos)     = __floats2half2_rn(q.x * QS, q.y * QS);
        *(__half2*)(Qh + row * QKSTR + pos + 8) = __floats2half2_rn(q.z * QS, q.w * QS);
        *(__half2*)(Kh + row * QKSTR + pos)     = __floats2half2_rn(k.x, k.y);
        *(__half2*)(Kh + row * QKSTR + pos + 8) = __floats2half2_rn(k.z, k.w);
        uint2 vv;
        vv.x = pack_h2(v.x, v.y);
        vv.y = pack_h2(v.z, v.w);
        *(uint2*)(Vh + row * VSTR + c4) = vv;   // one STS.64 (8B aligned)
    }
    __syncthreads();

    const int warp = tid >> 5;       // 0..8 -> m-tile
    const int lane = tid & 31;
    const int qr = lane >> 2;
    const int qc = lane & 3;
    const int m0 = warp * 16;

    // ---- Q A-fragments: ONE LDS.128 per row covers all 32 d ----
    const uint4 A0 = *(const uint4*)(Qh + (m0 + qr    ) * QKSTR + qc * 8);
    const uint4 A1 = *(const uint4*)(Qh + (m0 + qr + 8) * QKSTR + qc * 8);

    // ---- V ldmatrix lane base ----
    const unsigned vu = (unsigned)__cvta_generic_to_shared(Vh);
    const int blk = lane >> 3;
    const int rowi = lane & 7;
    const unsigned vbase = vu + (((blk & 1) * 8 + rowi) * VSTR + (blk >> 1) * 8) * 2;

    // ---- fragment-ordered mask pointer for this warp ----
    const float4* mp = MaskPerm + (h * 9 + warp) * 18 * 32 + lane;

    float* obase = out + (size_t)b * (NSEQ * 128) + h * 32;

    float o[4][4];
    #pragma unroll
    for (int dt = 0; dt < 4; dt++) {
        o[dt][0] = 0.f; o[dt][1] = 0.f; o[dt][2] = 0.f; o[dt][3] = 0.f;
    }
    float l0 = 0.f, l1 = 0.f;

    // ---- stream over 144 key cols: 9 chunks x 2 n-tiles (1 k16 PV step each) ----
    #pragma unroll
    for (int ch = 0; ch < 9; ch++) {
        float acc[2][4];

        // acc initialized from pre-scaled mask; mma accumulates S*log2e on top
        *(float4*)acc[0] = mp[(ch * 2    ) * 32];
        *(float4*)acc[1] = mp[(ch * 2 + 1) * 32];
        #pragma unroll
        for (int j = 0; j < 2; j++) {
            const int n0 = (ch * 2 + j) * 8;
            const uint4 B = *(const uint4*)(Kh + (n0 + qr) * QKSTR + qc * 8);
            float* a = acc[j];
            mma_f16(a, A0.x, A1.x, A0.y, A1.y, B.x, B.y);   // d 0..15
            mma_f16(a, A0.z, A1.z, A0.w, A1.w, B.z, B.w);   // d 16..31
        }

        // P = 2^acc  (== exp(S + mask - 4)); row sums in f32
        #pragma unroll
        for (int j = 0; j < 2; j++) {
            float* a = acc[j];
            a[0] = ex2f(a[0]); a[1] = ex2f(a[1]);
            a[2] = ex2f(a[2]); a[3] = ex2f(a[3]);
            l0 += a[0] + a[1];
            l1 += a[2] + a[3];
        }

        // O += P @ V: fp16 C-frag IS the A-frag layout -> pack only, no shfl
        const unsigned pa0 = pack_h2(acc[0][0], acc[0][1]);
        const unsigned pa1 = pack_h2(acc[0][2], acc[0][3]);
        const unsigned pa2 = pack_h2(acc[1][0], acc[1][1]);
        const unsigned pa3 = pack_h2(acc[1][2], acc[1][3]);
        const unsigned addr = vbase + ch * (16 * VSTR * 2);
        unsigned vb0, vb1, vb2, vb3, vb4, vb5, vb6, vb7;
        ldsm4t(vb0, vb1, vb2, vb3, addr);        // d 0..15
        ldsm4t(vb4, vb5, vb6, vb7, addr + 32);   // d 16..31
        mma_f16(o[0], pa0, pa1, pa2, pa3, vb0, vb1);
        mma_f16(o[1], pa0, pa1, pa2, pa3, vb2, vb3);
        mma_f16(o[2], pa0, pa1, pa2, pa3, vb4, vb5);
        mma_f16(o[3], pa0, pa1, pa2, pa3, vb6, vb7);
    }

    // ---- normalize (quad reductions) + store ----
    l0 += __shfl_xor_sync(0xffffffffu, l0, 1);
    l0 += __shfl_xor_sync(0xffffffffu, l0, 2);
    l1 += __shfl_xor_sync(0xffffffffu, l1, 1);
    l1 += __shfl_xor_sync(0xffffffffu, l1, 2);
    const float i0 = 1.f / l0;
    const float i1 = 1.f / l1;

    #pragma unroll
    for (int dt = 0; dt < 4; dt++) {
        const int d = dt * 8 + 2 * qc;
        float2* p0 = (float2*)(obase + (m0 + qr    ) * 128 + d);
        float2* p1 = (float2*)(obase + (m0 + qr + 8) * 128 + d);
        *p0 = make_float2(o[dt][0] * i0, o[dt][1] * i0);
        *p1 = make_float2(o[dt][2] * i1, o[dt][3] * i1);
    }
}

extern "C" void kernel_launch(void* const* d_in, const int* in_sizes, int n_in,
                              void* d_out, int out_size)
{
    const float* qkv  = (const float*)d_in[0];
    const float* mask = (const float*)d_in[1];
    float* out = (float*)d_out;

    mask_perm_kernel<<<(MPERM_ENTRIES + 255) / 256, 256>>>(mask);

    cudaFuncSetAttribute(attn_kernel,
                         cudaFuncAttributeMaxDynamicSharedMemorySize, SMEM_BYTES);
    attn_kernel<<<2048 * 4, 288, SMEM_BYTES>>>(qkv, out);
}